// round 9
// baseline (speedup 1.0000x reference)
#include <cuda_runtime.h>
#include <cuda_bf16.h>
#include <cstdint>

// ---------------------------------------------------------------------------
// Problem dims
// ---------------------------------------------------------------------------
#define NIN   128
#define NHID  256
#define NDEC  512
#define NOUT  10
#define BATCH 32
#define NSET  4096

#define TM       64                     // rows per tile
#define NTILES   (BATCH * NSET / TM)    // 2048
#define THREADS  256                    // 8 warps: 2 (row halves of 32) x 4 (col quarters)
#define GRID_ENC 296                    // persistent: 2 CTAs per SM on 148 SMs

// Weight image: k-chunks of 32, each chunk = hi(16KB) + lo(16KB) = 32KB, pre-swizzled
#define CHUNK_BYTES 32768
#define NCHUNKS     20                  // L1:4  L2:8  L3:8  (contiguous)
#define IMG_BYTES   (NCHUNKS * CHUNK_BYTES)

// SMEM layout (bytes) — total 101376 (< 113KB => 2 CTAs/SM)
#define SMEM_A     0                    // 64 rows x 512B (256 bf16), XOR-swizzled
#define SMEM_W     32768                // 2 slots x 32KB ring
#define SMEM_BIAS  98304                // 256 floats
#define SMEM_RED   99328                // 2 x 256 floats
#define SMEM_TOTAL 101376

// ---------------------------------------------------------------------------
// Device globals (static; fully rewritten every launch)
// ---------------------------------------------------------------------------
__device__ __align__(128) uint8_t g_wimg[IMG_BYTES];
__device__ float g_partial[NTILES * NHID];

// ---------------------------------------------------------------------------
// PTX helpers (baseline sm_80-era PTX only: safe at compute_103 target)
// ---------------------------------------------------------------------------
__device__ __forceinline__ uint32_t smem_u32(const void* p) {
    uint32_t a;
    asm("{ .reg .u64 t; cvta.to.shared.u64 t, %1; cvt.u32.u64 %0, t; }" : "=r"(a) : "l"(p));
    return a;
}

__device__ __forceinline__ void ldsm4(uint32_t r[4], uint32_t addr) {
    asm volatile("ldmatrix.sync.aligned.m8n8.x4.shared.b16 {%0,%1,%2,%3}, [%4];"
        : "=r"(r[0]), "=r"(r[1]), "=r"(r[2]), "=r"(r[3]) : "r"(addr));
}

__device__ __forceinline__ void mma16(float c[4], const uint32_t a[4], uint32_t b0, uint32_t b1) {
    asm volatile(
        "mma.sync.aligned.m16n8k16.row.col.f32.bf16.bf16.f32 "
        "{%0,%1,%2,%3},{%4,%5,%6,%7},{%8,%9},{%0,%1,%2,%3};"
        : "+f"(c[0]), "+f"(c[1]), "+f"(c[2]), "+f"(c[3])
        : "r"(a[0]), "r"(a[1]), "r"(a[2]), "r"(a[3]), "r"(b0), "r"(b1));
}

#define CP16(dst, src) \
    asm volatile("cp.async.cg.shared.global [%0], [%1], 16;" :: "r"(dst), "l"(src))
#define CP_COMMIT() asm volatile("cp.async.commit_group;" ::: "memory")
#define CP_WAIT0()  asm volatile("cp.async.wait_group 0;"  ::: "memory")

// B-image swizzle: rows are 64B (32 bf16 k-values); mask stays below the row
// stride (bits 4-5 only), applied to the k-offset on both store and load.
__device__ __forceinline__ uint32_t bmask(int n) { return ((uint32_t)(n >> 1) & 3u) << 4; }

// ---------------------------------------------------------------------------
// Weight pre-convert (once per launch): fp32 W[K,256] -> swizzled bf16 hi/lo image.
// One thread per packed uint32 slot; stores fully coalesced.
// ---------------------------------------------------------------------------
__global__ void __launch_bounds__(256)
convert_weights(const float* __restrict__ W1, const float* __restrict__ W2,
                const float* __restrict__ W3)
{
    int idx = blockIdx.x * 256 + threadIdx.x;    // 0 .. 81919 (uint32 slots)
    int chunk = idx >> 12;                       // 4096 slots per chunk
    int rem   = idx & 4095;
    int n     = rem >> 4;                        // 0..255
    int s     = rem & 15;                        // uint32 slot within 64B row

    const float* W; int kbase;
    if (chunk < 4)       { W = W1; kbase = chunk * 32; }
    else if (chunk < 12) { W = W2; kbase = (chunk - 4) * 32; }
    else                 { W = W3; kbase = (chunk - 12) * 32; }

    // inverse swizzle: stored byte = (k*2) ^ bm  =>  k*2 = (4s) ^ bm
    uint32_t bm = bmask(n);
    int k0 = (int)((((uint32_t)(4 * s)) ^ bm) >> 1);   // even; pair is (k0, k0+1)
    float w0 = W[(kbase + k0) * 256 + n];
    float w1 = W[(kbase + k0 + 1) * 256 + n];

    __nv_bfloat16 h0 = __float2bfloat16(w0);
    __nv_bfloat16 h1 = __float2bfloat16(w1);
    __nv_bfloat16 l0 = __float2bfloat16(w0 - __bfloat162float(h0));
    __nv_bfloat16 l1 = __float2bfloat16(w1 - __bfloat162float(h1));

    uint32_t hi = ((uint32_t)*reinterpret_cast<uint16_t*>(&h1) << 16) |
                   (uint32_t)*reinterpret_cast<uint16_t*>(&h0);
    uint32_t lo = ((uint32_t)*reinterpret_cast<uint16_t*>(&l1) << 16) |
                   (uint32_t)*reinterpret_cast<uint16_t*>(&l0);

    uint8_t* cb = g_wimg + (size_t)chunk * CHUNK_BYTES + n * 64 + 4 * s;
    *(uint32_t*)cb           = hi;
    *(uint32_t*)(cb + 16384) = lo;
}

// ---------------------------------------------------------------------------
// Encoder: persistent, 2 CTAs/SM, TM=64 tiles, 3 fused layers per tile.
// Single barrier per chunk: at chunk top, wait(chunk g) -> barrier -> issue
// chunk g+1 into the just-freed slot -> MMA on slot g&1. Weight stream is
// periodic (period 20, even) so ring parity is seamless across tiles.
// ---------------------------------------------------------------------------
__global__ void __launch_bounds__(THREADS, 2)
encoder_kernel(const float* __restrict__ x,
               const float* __restrict__ b1, const float* __restrict__ b2,
               const float* __restrict__ b3)
{
    extern __shared__ char smem[];
    const uint32_t sb = smem_u32(smem);
    const int tid  = threadIdx.x;
    const int lane = tid & 31;
    const int wid  = tid >> 5;
    const int wm   = wid >> 2;          // 0..1  (row half, 32 rows)
    const int wn   = wid & 3;           // 0..3  (col quarter, 64 cols)
    float* bias_s = (float*)(smem + SMEM_BIAS);
    float* red    = (float*)(smem + SMEM_RED);

    // --- prologue: issue chunk 0 only (chunk 1 is issued at chunk 0's top) ---
    {
        const uint8_t* src = g_wimg;
        uint32_t dst = sb + SMEM_W;
#pragma unroll
        for (int i = 0; i < 8; i++)
            CP16(dst + (tid + i * 256) * 16, src + (tid + i * 256) * 16);
        CP_COMMIT();
    }

    // --- per-thread ldmatrix address precompute ---
    uint32_t a_base[2], a_xm[2];
    {
        int r0 = wm * 32 + (lane & 15);
#pragma unroll
        for (int mt = 0; mt < 2; mt++) {
            int r = r0 + mt * 16;
            a_base[mt] = sb + SMEM_A + (uint32_t)(r * 512);
            a_xm[mt]   = ((uint32_t)(r & 7)) << 4;
        }
    }
    const uint32_t a_h16 = (uint32_t)(lane >> 4) * 16;
    uint32_t b_off[4], b_xm[4];
    {
        int n0 = wn * 64 + (lane & 7) + ((lane >> 4) << 3);
#pragma unroll
        for (int q = 0; q < 4; q++) {
            int n = n0 + q * 16;
            b_off[q] = (uint32_t)(n * 64);
            b_xm[q]  = bmask(n);
        }
    }
    const uint32_t b_h16 = ((uint32_t)(lane >> 3) & 1) * 16;

    const float* biases[3] = { b1, b2, b3 };
    const int    ncs[3]    = { 4, 8, 8 };
    const int    gg = lane >> 2, t = lane & 3;

    for (int tile = blockIdx.x; tile < NTILES; tile += GRID_ENC) {
        // --- stage x tile [64 x 128] fp32 -> bf16 into swizzled A (512B rows) ---
        {
            const float4* xt = (const float4*)(x + (size_t)tile * TM * NIN);
#pragma unroll
            for (int i = tid; i < TM * NIN / 4; i += THREADS) {
                float4 v = xt[i];
                int p = i * 4;
                int r = p >> 7, cc = p & 127;
                uint32_t off = ((uint32_t)(r * 512 + cc * 2)) ^ ((uint32_t)(r & 7) << 4);
                __nv_bfloat162 lo2 = __floats2bfloat162_rn(v.x, v.y);
                __nv_bfloat162 hi2 = __floats2bfloat162_rn(v.z, v.w);
                uint2 u;
                u.x = *reinterpret_cast<uint32_t*>(&lo2);
                u.y = *reinterpret_cast<uint32_t*>(&hi2);
                *(uint2*)(smem + SMEM_A + off) = u;
            }
        }
        __syncthreads();                 // x staged before layer-1 MMAs

        int g = 0;                       // within-tile chunk index (0..19)
        for (int L = 0; L < 3; L++) {
            bias_s[tid] = biases[L][tid];

            float c[2][8][4];
#pragma unroll
            for (int mt = 0; mt < 2; mt++)
#pragma unroll
                for (int nt = 0; nt < 8; nt++)
#pragma unroll
                    for (int e = 0; e < 4; e++) c[mt][nt][e] = 0.f;

            const int nc = ncs[L];
            for (int lk = 0; lk < nc; lk++, g++) {
                CP_WAIT0();              // chunk g landed in slot g&1
                __syncthreads();         // all warps done reading slot (g+1)&1 (chunk g-1)

                {                        // issue chunk (g+1) mod 20 into slot (g+1)&1
                    int nxt = g + 1; if (nxt >= NCHUNKS) nxt -= NCHUNKS;
                    uint32_t dst = sb + SMEM_W + (uint32_t)(nxt & 1) * CHUNK_BYTES;
                    const uint8_t* src = g_wimg + (size_t)nxt * CHUNK_BYTES;
#pragma unroll
                    for (int i = 0; i < 8; i++)
                        CP16(dst + (tid + i * 256) * 16, src + (tid + i * 256) * 16);
                }
                CP_COMMIT();

                const uint32_t wslot = sb + SMEM_W + (uint32_t)(g & 1) * CHUNK_BYTES;
#pragma unroll
                for (int ks = 0; ks < 2; ks++) {
                    uint32_t a[2][4];
                    const uint32_t kkA = (uint32_t)(lk * 64 + ks * 32) + a_h16;
#pragma unroll
                    for (int mt = 0; mt < 2; mt++)
                        ldsm4(a[mt], a_base[mt] + (kkA ^ a_xm[mt]));

                    const uint32_t kkB = (uint32_t)(ks * 32) + b_h16;
#pragma unroll
                    for (int q = 0; q < 4; q++) {
                        uint32_t bh[4], bl[4];
                        ldsm4(bh, wslot + b_off[q] + (kkB ^ b_xm[q]));
                        ldsm4(bl, wslot + 16384 + b_off[q] + (kkB ^ b_xm[q]));
                        const int nt0 = 2 * q;
#pragma unroll
                        for (int mt = 0; mt < 2; mt++) {
                            mma16(c[mt][nt0],     a[mt], bh[0], bh[1]);
                            mma16(c[mt][nt0 + 1], a[mt], bh[2], bh[3]);
                        }
#pragma unroll
                        for (int mt = 0; mt < 2; mt++) {
                            mma16(c[mt][nt0],     a[mt], bl[0], bl[1]);
                            mma16(c[mt][nt0 + 1], a[mt], bl[2], bl[3]);
                        }
                    }
                }
            }

            if (L < 2) {
                __syncthreads();         // all warps' MMA reads of A done
                // epilogue: bias + relu -> bf16, rewrite A in place
#pragma unroll
                for (int mt = 0; mt < 2; mt++) {
                    const int r0 = wm * 32 + mt * 16 + gg;
                    const int r1 = r0 + 8;
                    const uint32_t x0 = ((uint32_t)(r0 & 7)) << 4;
                    const uint32_t x1 = ((uint32_t)(r1 & 7)) << 4;
#pragma unroll
                    for (int nt = 0; nt < 8; nt++) {
                        const int col = wn * 64 + nt * 8 + 2 * t;
                        const float bb0 = bias_s[col], bb1 = bias_s[col + 1];
                        __nv_bfloat162 p0 = __floats2bfloat162_rn(
                            fmaxf(c[mt][nt][0] + bb0, 0.f), fmaxf(c[mt][nt][1] + bb1, 0.f));
                        __nv_bfloat162 p1 = __floats2bfloat162_rn(
                            fmaxf(c[mt][nt][2] + bb0, 0.f), fmaxf(c[mt][nt][3] + bb1, 0.f));
                        uint32_t o0 = ((uint32_t)(r0 * 512 + col * 2)) ^ x0;
                        uint32_t o1 = ((uint32_t)(r1 * 512 + col * 2)) ^ x1;
                        *(uint32_t*)(smem + SMEM_A + o0) = *reinterpret_cast<uint32_t*>(&p0);
                        *(uint32_t*)(smem + SMEM_A + o1) = *reinterpret_cast<uint32_t*>(&p1);
                    }
                }
                __syncthreads();         // epilogue done before next layer's reads
            } else {
                // final: bias + relu + column sums over this warp's 32 rows
#pragma unroll
                for (int nt = 0; nt < 8; nt++) {
                    const int col = wn * 64 + nt * 8 + 2 * t;
                    const float bb0 = bias_s[col], bb1 = bias_s[col + 1];
                    float s0 = 0.f, s1 = 0.f;
#pragma unroll
                    for (int mt = 0; mt < 2; mt++) {
                        s0 += fmaxf(c[mt][nt][0] + bb0, 0.f) + fmaxf(c[mt][nt][2] + bb0, 0.f);
                        s1 += fmaxf(c[mt][nt][1] + bb1, 0.f) + fmaxf(c[mt][nt][3] + bb1, 0.f);
                    }
#pragma unroll
                    for (int off = 16; off >= 4; off >>= 1) {
                        s0 += __shfl_down_sync(0xffffffffu, s0, off);
                        s1 += __shfl_down_sync(0xffffffffu, s1, off);
                    }
                    if (lane < 4) {      // lane == t; full 32-row sums for this warp
                        red[wm * 256 + col]     = s0;
                        red[wm * 256 + col + 1] = s1;
                    }
                }
                __syncthreads();
                g_partial[(size_t)tile * NHID + tid] = red[tid] + red[256 + tid];
                __syncthreads();         // red consumed before next tile reuses it
            }
        }
    }
}

// ---------------------------------------------------------------------------
// Fused decoder: mean->square->d1->d2->d3, one CTA per batch, 512 threads.
// All weight streams k-outer, coalesced row-major. Exact fp32.
// ---------------------------------------------------------------------------
__global__ void __launch_bounds__(512, 1)
decoder_kernel(const float* __restrict__ D1, const float* __restrict__ c1,
               const float* __restrict__ D2, const float* __restrict__ c2,
               const float* __restrict__ D3, const float* __restrict__ c3,
               float* __restrict__ out)
{
    __shared__ float p_s[NHID];
    __shared__ float d1_s[NDEC];
    __shared__ float d2_s[NDEC];
    __shared__ float wred[16 * NOUT];
    const int b = blockIdx.x, tid = threadIdx.x;
    const int lane = tid & 31, wrp = tid >> 5;

    // mean over 64 tile-partials (deterministic fixed order), then p = relu(m*m)
    if (tid < NHID) {
        const int tiles = NSET / TM;     // 64
        float s = 0.f;
        const float* base = g_partial + (size_t)(b * tiles) * NHID + tid;
#pragma unroll 8
        for (int i = 0; i < tiles; i++) s += base[(size_t)i * NHID];
        const float m = s * (1.0f / NSET);
        p_s[tid] = fmaxf(m * m, 0.f);
    }
    __syncthreads();

    // d1 = relu(p @ D1 + c1): thread j owns output j; k-outer coalesced stream
    {
        float acc = 0.f;
        const float* w = D1 + tid;
#pragma unroll 8
        for (int k = 0; k < NHID; k++) acc += p_s[k] * w[(size_t)k * NDEC];
        d1_s[tid] = fmaxf(acc + c1[tid], 0.f);
    }
    __syncthreads();

    // d2 = relu(d1 @ D2 + c2)
    {
        float acc = 0.f;
        const float* w = D2 + tid;
#pragma unroll 8
        for (int k = 0; k < NDEC; k++) acc += d1_s[k] * w[(size_t)k * NDEC];
        d2_s[tid] = fmaxf(acc + c2[tid], 0.f);
    }
    __syncthreads();

    // d3: thread k contributes d2[k]*D3[k][:]; warp-shfl + smem tree reduce
    {
        float part[NOUT];
        const float v = d2_s[tid];
        const float* w = D3 + (size_t)tid * NOUT;
#pragma unroll
        for (int o = 0; o < NOUT; o++) part[o] = v * w[o];
#pragma unroll
        for (int off = 16; off >= 1; off >>= 1)
#pragma unroll
            for (int o = 0; o < NOUT; o++)
                part[o] += __shfl_down_sync(0xffffffffu, part[o], off);
        if (lane == 0)
#pragma unroll
            for (int o = 0; o < NOUT; o++) wred[wrp * NOUT + o] = part[o];
    }
    __syncthreads();
    if (tid < NOUT) {
        float s = 0.f;
#pragma unroll
        for (int w = 0; w < 16; w++) s += wred[w * NOUT + tid];
        out[b * NOUT + tid] = c3[tid] + s;
    }
}

// ---------------------------------------------------------------------------
// fp8 capability probe: compiles an e4m3 mma.sync; guarded so it never executes
// for real data (c3 values are ~1e-1 magnitude, never 1e20). If this file
// passes the bench, sm_103-plain supports fp8 mma and the next iteration can
// replace the lo-product with e4m3 at m16n8k32 (half the lo instructions).
// ---------------------------------------------------------------------------
__global__ void __launch_bounds__(32)
fp8_probe(const float* __restrict__ c3)
{
    if (c3[0] == 1.2345678e+20f) {       // uniform, deterministic, always false
        uint32_t a0 = threadIdx.x, a1 = 1u, a2 = 2u, a3 = 3u, b0 = 4u, b1 = 5u;
        float d0 = 0.f, d1 = 0.f, d2 = 0.f, d3 = 0.f;
        asm volatile(
            "mma.sync.aligned.m16n8k32.row.col.f32.e4m3.e4m3.f32 "
            "{%0,%1,%2,%3},{%4,%5,%6,%7},{%8,%9},{%0,%1,%2,%3};"
            : "+f"(d0), "+f"(d1), "+f"(d2), "+f"(d3)
            : "r"(a0), "r"(a1), "r"(a2), "r"(a3), "r"(b0), "r"(b1));
        g_partial[0] = d0 + d1 + d2 + d3;
    }
}

// ---------------------------------------------------------------------------
extern "C" void kernel_launch(void* const* d_in, const int* in_sizes, int n_in,
                              void* d_out, int out_size)
{
    (void)in_sizes; (void)n_in; (void)out_size;
    const float* x  = (const float*)d_in[0];
    const float* W1 = (const float*)d_in[1];
    const float* b1 = (const float*)d_in[2];
    const float* W2 = (const float*)d_in[3];
    const float* b2 = (const float*)d_in[4];
    const float* W3 = (const float*)d_in[5];
    const float* b3 = (const float*)d_in[6];
    const float* D1 = (const float*)d_in[7];
    const float* c1 = (const float*)d_in[8];
    const float* D2 = (const float*)d_in[9];
    const float* c2 = (const float*)d_in[10];
    const float* D3 = (const float*)d_in[11];
    const float* c3 = (const float*)d_in[12];

    cudaFuncSetAttribute(encoder_kernel, cudaFuncAttributeMaxDynamicSharedMemorySize, SMEM_TOTAL);

    convert_weights<<<320, 256>>>(W1, W2, W3);
    encoder_kernel<<<GRID_ENC, THREADS, SMEM_TOTAL>>>(x, b1, b2, b3);
    decoder_kernel<<<BATCH, 512>>>(D1, c1, D2, c2, D3, c3, (float*)d_out);
    fp8_probe<<<1, 32>>>(c3);
}